// round 14
// baseline (speedup 1.0000x reference)
#include <cuda_runtime.h>
#include <cstdint>
#include <cstddef>

#define NMAT   256
#define NFREQ  33
#define SLICE  (NMAT*NMAT)
#define NTUBE  (8*SLICE)

__device__ float g_Ar[8*NFREQ*SLICE];   // [slice][i*256+j]  (tf32-rounded)
__device__ float g_Ai[8*NFREQ*SLICE];
__device__ float g_As[8*NFREQ*SLICE];   // rna(re+im)
__device__ float g_Br[8*NFREQ*SLICE];   // [slice][n*256+j]
__device__ float g_Bi[8*NFREQ*SLICE];
__device__ float g_Bs[8*NFREQ*SLICE];
__device__ float g_Cr[8*NFREQ*SLICE];   // [slice][i*256+n]  (fp32)
__device__ float g_Ci[8*NFREQ*SLICE];

// ---------------- compile-time trig ----------------
constexpr double PI_D = 3.14159265358979323846264338327950288;
constexpr double tay_sin(double x){ double t=x,s=x; for(int i=1;i<12;i++){ t*=-(x*x)/double((2*i)*(2*i+1)); s+=t; } return s; }
constexpr double tay_cos(double x){ double t=1,s=1; for(int i=1;i<12;i++){ t*=-(x*x)/double((2*i-1)*(2*i)); s+=t; } return s; }
constexpr double c_cos64(int n){ int m=((n%64)+64)%64; double sg=1; if(m>=32){m-=32;sg=-sg;} if(m>16){m=32-m;sg=-sg;} return sg*tay_cos(PI_D*m/32.0); }
constexpr double c_sin64(int n){ int m=((n%64)+64)%64; double sg=1; if(m>=32){m-=32;sg=-sg;} if(m>16){m=32-m;} return sg*tay_sin(PI_D*m/32.0); }

template<int N> struct CW   { static constexpr float v = (float)c_cos64(N); };
template<int N> struct NSW  { static constexpr float v = (float)(-c_sin64(N)); };
template<int N> struct ICW  { static constexpr float v = (float)(c_cos64(N)/32.0); };
template<int N> struct NISW { static constexpr float v = (float)(-c_sin64(N)/32.0); };

__device__ __forceinline__ float tf32f(float x){
    uint32_t u; asm("cvt.rna.tf32.f32 %0, %1;" : "=r"(u) : "f"(x));
    return __uint_as_float(u);
}

// ---------------- forward DFT (radix-2 folded) ----------------
template<int M,int S> struct F_E {
    static __device__ __forceinline__ float f(const float (&E)[17]){
        return fmaf(E[S], CW<(2*M*S)&63>::v, F_E<M,S-1>::f(E)); }
};
template<int M> struct F_E<M,0> {
    static __device__ __forceinline__ float f(const float (&E)[17]){ return E[0]; }
};
template<int M,int S> struct F_F {
    static __device__ __forceinline__ float f(const float (&F)[16]){
        return fmaf(F[S], CW<((2*M+1)*S)&63>::v, F_F<M,S-1>::f(F)); }
};
template<int M> struct F_F<M,0> {
    static __device__ __forceinline__ float f(const float (&F)[16]){ return F[0]; }
};
template<int M,int S> struct F_P {
    static __device__ __forceinline__ float f(const float (&P)[16]){
        return fmaf(P[S], NSW<(2*M*S)&63>::v, F_P<M,S-1>::f(P)); }
};
template<int M> struct F_P<M,0> {
    static __device__ __forceinline__ float f(const float (&)[16]){ return 0.0f; }
};
template<int M,int S> struct F_Q {
    static __device__ __forceinline__ float f(const float (&Q)[17]){
        return fmaf(Q[S], NSW<((2*M+1)*S)&63>::v, F_Q<M,S-1>::f(Q)); }
};
template<int M> struct F_Q<M,0> {
    static __device__ __forceinline__ float f(const float (&)[17]){ return 0.0f; }
};

template<int M> struct Fwd2 {
    static __device__ __forceinline__ void run(const float (&E)[17], const float (&F)[16],
                                               const float (&P)[16], const float (&Q)[17],
                                               float* __restrict__ pr, float* __restrict__ pi,
                                               float* __restrict__ ps){
        {
            float re = tf32f(F_E<M,16>::f(E));
            float im = tf32f(F_P<M,15>::f(P));
            pr[(size_t)(2*M)<<16] = re;
            pi[(size_t)(2*M)<<16] = im;
            ps[(size_t)(2*M)<<16] = tf32f(re + im);
        }
        if constexpr (M < 16){
            float re = tf32f(F_F<M,15>::f(F));
            float im = tf32f(F_Q<M,16>::f(Q));
            pr[(size_t)(2*M+1)<<16] = re;
            pi[(size_t)(2*M+1)<<16] = im;
            ps[(size_t)(2*M+1)<<16] = tf32f(re + im);
        }
        Fwd2<M-1>::run(E, F, P, Q, pr, pi, ps);
    }
};
template<> struct Fwd2<-1> {
    static __device__ __forceinline__ void run(const float (&)[17], const float (&)[16],
                                               const float (&)[16], const float (&)[17],
                                               float*, float*, float*){}
};

__device__ __forceinline__ void fwd_fold_run(const float* __restrict__ a,
                                             float* __restrict__ pr, float* __restrict__ pi,
                                             float* __restrict__ ps){
    float E[17], F[16], P[16], Q[17];
    {
        float a0=a[0], a32=a[32], a16=a[16], a48=a[48];
        E[0]=a0+a32; F[0]=a0-a32; E[16]=a16+a48; Q[16]=a16-a48;
#pragma unroll
        for (int s = 1; s < 16; s++){
            float p1=a[s], p2=a[64-s], p3=a[32-s], p4=a[32+s];
            float eA=p1+p2, eB=p3+p4, oA=p1-p2, oB=p3-p4;
            E[s]=eA+eB; F[s]=eA-eB; P[s]=oA-oB; Q[s]=oA+oB;
        }
    }
    Fwd2<16>::run(E, F, P, Q, pr, pi, ps);
}

// ---------------- inverse DFT chains (radix-2 folded) ----------------
template<int U,int K> struct I_EC {
    static __device__ __forceinline__ float f(const float (&RP)[16]){
        return fmaf(RP[K], ICW<(2*U*K)&63>::v, I_EC<U,K-1>::f(RP)); }
};
template<int U> struct I_EC<U,0> {
    static __device__ __forceinline__ float f(const float (&)[16]){ return 0.0f; }
};
template<int U,int K> struct I_ES {
    static __device__ __forceinline__ float f(const float (&IM)[16]){
        return fmaf(IM[K], NISW<(2*U*K)&63>::v, I_ES<U,K-1>::f(IM)); }
};
template<int U> struct I_ES<U,0> {
    static __device__ __forceinline__ float f(const float (&)[16]){ return 0.0f; }
};
template<int U,int K> struct I_OC {
    static __device__ __forceinline__ float f(const float (&RM)[16]){
        return fmaf(RM[K], ICW<((2*U+1)*K)&63>::v, I_OC<U,K-1>::f(RM)); }
};
template<int U> struct I_OC<U,0> {
    static __device__ __forceinline__ float f(const float (&)[16]){ return 0.0f; }
};
template<int U,int K> struct I_OS {
    static __device__ __forceinline__ float f(const float (&IP)[16]){
        return fmaf(IP[K], NISW<((2*U+1)*K)&63>::v, I_OS<U,K-1>::f(IP)); }
};
template<int U> struct I_OS<U,0> {
    static __device__ __forceinline__ float f(const float (&)[16]){ return 0.0f; }
};

// even outputs only (t = 2U)
template<int U> struct InvE {
    static __device__ __forceinline__ void run(float R0, float R16, float R32,
                                               const float (&RP)[16], const float (&IM)[16],
                                               float* __restrict__ sw){
        float Ev = I_EC<U,15>::f(RP);
        Ev = fmaf(R0 + R32, 0.015625f, Ev);
        Ev = fmaf(R16, (U & 1) ? -0.03125f : 0.03125f, Ev);
        float Ov = I_ES<U,15>::f(IM);
        if constexpr (U == 0){
            sw[0] = Ev + Ov;
        } else {
            sw[2*U]      = Ev + Ov;
            sw[64 - 2*U] = Ev - Ov;
        }
        InvE<U-1>::run(R0, R16, R32, RP, IM, sw);
    }
};
template<> struct InvE<-1> {
    static __device__ __forceinline__ void run(float, float, float,
                                               const float (&)[16], const float (&)[16], float*){}
};

// odd outputs only (t = 2U+1)
template<int U> struct InvO {
    static __device__ __forceinline__ void run(float RD, float I16,
                                               const float (&RM)[16], const float (&IP)[16],
                                               float* __restrict__ sw){
        float Ev = I_OC<U,15>::f(RM);
        Ev = fmaf(RD, 0.015625f, Ev);
        float Ov = I_OS<U,15>::f(IP);
        Ov = fmaf(I16, (U & 1) ? 0.03125f : -0.03125f, Ov);
        sw[2*U + 1]  = Ev + Ov;
        sw[63 - 2*U] = Ev - Ov;
        InvO<U-1>::run(RD, I16, RM, IP, sw);
    }
};
template<> struct InvO<-1> {
    static __device__ __forceinline__ void run(float, float,
                                               const float (&)[16], const float (&)[16], float*){}
};

// ---------------- Stage 1a: forward rDFT for A ----------------
__global__ void __launch_bounds__(128) dft_fwd_A(const float* __restrict__ in){
    __shared__ float sm[128*67];
    const int tid = threadIdx.x;
    const float4* in4 = (const float4*)(in + (size_t)blockIdx.x * 8192);
#pragma unroll
    for (int h = 0; h < 16; h++){
        int l4 = h*128 + tid;
        float4 v = in4[l4];
        int tube = l4 >> 4;
        int s = (l4 & 15) * 4;
        float* p = &sm[tube*67 + s];
        p[0]=v.x; p[1]=v.y; p[2]=v.z; p[3]=v.w;
    }
    __syncthreads();

    const int T   = blockIdx.x*128 + tid;
    const size_t off = ((size_t)(T >> 16) * NFREQ << 16) + (T & 65535);
    fwd_fold_run(&sm[tid*67], g_Ar + off, g_Ai + off, g_As + off);
}

// ---------------- Stage 1b: forward rDFT for B, transposed write [k][n][j] ----------------
__global__ void __launch_bounds__(128) dft_fwd_B(const float* __restrict__ in){
    __shared__ float sm[128*67];
    const int tid = threadIdx.x;
    const int blk = blockIdx.x;
    const int b   = blk >> 9;
    const int rem = blk & 511;
    const int j0  = (rem >> 6) << 5;
    const int n0  = (rem & 63) << 2;
    const float4* base4 = (const float4*)(in + (size_t)b * SLICE * 64);
#pragma unroll
    for (int h = 0; h < 16; h++){
        int l4 = h*128 + tid;
        int jl  = l4 >> 6;
        int r64 = l4 & 63;
        float4 v = base4[(size_t)((j0 + jl)*NMAT + n0)*16 + r64];
        int tube = (r64 >> 4)*32 + jl;
        int s = (r64 & 15) * 4;
        float* p = &sm[tube*67 + s];
        p[0]=v.x; p[1]=v.y; p[2]=v.z; p[3]=v.w;
    }
    __syncthreads();

    const int jg = j0 + (tid & 31);
    const int ng = n0 + (tid >> 5);
    const size_t off = ((size_t)b * NFREQ << 16) + ng*NMAT + jg;
    fwd_fold_run(&sm[tid*67], g_Br + off, g_Bi + off, g_Bs + off);
}

// ---------------- Stage 2: mma.sync tf32 Gauss complex GEMM ----------------
__device__ __forceinline__ uint32_t s2u(const void* p){
    uint32_t a;
    asm("{ .reg .u64 t; cvta.to.shared.u64 t, %1; cvt.u32.u64 %0, t; }" : "=r"(a) : "l"(p));
    return a;
}
#define CP16(dst, src) asm volatile("cp.async.cg.shared.global [%0], [%1], 16;" :: "r"(dst), "l"(src))
#define CPCOMMIT()     asm volatile("cp.async.commit_group;" ::: "memory")
#define CPWAIT1()      asm volatile("cp.async.wait_group 1;" ::: "memory")

__device__ __forceinline__ void mma_tf32(float* d, const uint32_t* a, const uint32_t* b){
    asm volatile("mma.sync.aligned.m16n8k8.row.col.f32.tf32.tf32.f32 "
        "{%0,%1,%2,%3}, {%4,%5,%6,%7}, {%8,%9}, {%0,%1,%2,%3};"
        : "+f"(d[0]), "+f"(d[1]), "+f"(d[2]), "+f"(d[3])
        : "r"(a[0]), "r"(a[1]), "r"(a[2]), "r"(a[3]), "r"(b[0]), "r"(b[1]));
}

// smem stage layout (bytes): A planes 128x36 fl, B planes 64x36 fl
#define ZPITCH 36
#define AS_RE  0
#define AS_IM  18432
#define AS_SU  36864
#define BS_RE  55296
#define BS_IM  64512
#define BS_SU  73728
#define ZSTAGE 82944
#define ZSMEM  (2*ZSTAGE)     // 165888

__global__ void __launch_bounds__(256, 1) zgemm_mma(){
    extern __shared__ char smemc[];
    const uint32_t sb = s2u(smemc);
    const int tid  = threadIdx.x;
    const int lane = tid & 31;
    const int wid  = tid >> 5;
    const int gid  = lane >> 2, tig = lane & 3;
    const int mwarp = wid >> 1;
    const int nwarp = wid & 1;

    const int slice = blockIdx.y;
    const int kf = slice % 33;
    const bool realk = (kf == 0) || (kf == 32);
    const int i0 = (blockIdx.x >> 2) * 128;
    const int n0 = (blockIdx.x & 3) * 64;

    const float* __restrict__ Ar = g_Ar + ((size_t)slice << 16) + (size_t)i0*NMAT;
    const float* __restrict__ Ai = g_Ai + ((size_t)slice << 16) + (size_t)i0*NMAT;
    const float* __restrict__ As = g_As + ((size_t)slice << 16) + (size_t)i0*NMAT;
    const float* __restrict__ Br = g_Br + ((size_t)slice << 16) + (size_t)n0*NMAT;
    const float* __restrict__ Bi = g_Bi + ((size_t)slice << 16) + (size_t)n0*NMAT;
    const float* __restrict__ Bs = g_Bs + ((size_t)slice << 16) + (size_t)n0*NMAT;
    float* __restrict__ Cr = g_Cr + ((size_t)slice << 16);
    float* __restrict__ Ci = g_Ci + ((size_t)slice << 16);

    float p1[2][4][4], p2[2][4][4], p3[2][4][4];
#pragma unroll
    for (int mt = 0; mt < 2; mt++)
#pragma unroll
        for (int nt = 0; nt < 4; nt++)
#pragma unroll
            for (int q = 0; q < 4; q++){ p1[mt][nt][q]=0.f; p2[mt][nt][q]=0.f; p3[mt][nt][q]=0.f; }

    int aRow[4], aK4[4], bRow[2], bK4[2];
#pragma unroll
    for (int h = 0; h < 4; h++){
        int lin = h*256 + tid;
        aRow[h] = lin >> 3; aK4[h] = (lin & 7) * 4;
    }
#pragma unroll
    for (int h = 0; h < 2; h++){
        int lin = h*256 + tid;
        bRow[h] = lin >> 3; bK4[h] = (lin & 7) * 4;
    }

    auto issue = [&](int c, int st){
        const uint32_t s0 = sb + st*ZSTAGE;
        const int kb = c*32;
#pragma unroll
        for (int h = 0; h < 4; h++){
            uint32_t d = s0 + (uint32_t)((aRow[h]*ZPITCH + aK4[h])*4);
            size_t g = (size_t)aRow[h]*NMAT + kb + aK4[h];
            CP16(d + AS_RE, Ar + g);
            if (!realk){
                CP16(d + AS_IM, Ai + g);
                CP16(d + AS_SU, As + g);
            }
        }
#pragma unroll
        for (int h = 0; h < 2; h++){
            uint32_t d = s0 + (uint32_t)((bRow[h]*ZPITCH + bK4[h])*4);
            size_t g = (size_t)bRow[h]*NMAT + kb + bK4[h];
            CP16(d + BS_RE, Br + g);
            if (!realk){
                CP16(d + BS_IM, Bi + g);
                CP16(d + BS_SU, Bs + g);
            }
        }
    };

    issue(0, 0); CPCOMMIT();
    issue(1, 1); CPCOMMIT();

    for (int c = 0; c < 8; c++){
        CPWAIT1();
        __syncthreads();
        const int st = c & 1;
        const float* AsRe = (const float*)(smemc + st*ZSTAGE + AS_RE);
        const float* AsIm = (const float*)(smemc + st*ZSTAGE + AS_IM);
        const float* AsSu = (const float*)(smemc + st*ZSTAGE + AS_SU);
        const float* BsRe = (const float*)(smemc + st*ZSTAGE + BS_RE);
        const float* BsIm = (const float*)(smemc + st*ZSTAGE + BS_IM);
        const float* BsSu = (const float*)(smemc + st*ZSTAGE + BS_SU);

#pragma unroll
        for (int kk = 0; kk < 32; kk += 8){
            uint32_t ar[2][4], ai[2][4], as_[2][4];
#pragma unroll
            for (int mt = 0; mt < 2; mt++){
                int r0 = mwarp*32 + mt*16 + gid;
#pragma unroll
                for (int q = 0; q < 4; q++){
                    int rr = r0 + (q & 1)*8;
                    int cc = kk + tig + (q >> 1)*4;
                    ar[mt][q] = __float_as_uint(AsRe[rr*ZPITCH + cc]);
                    if (!realk){
                        ai[mt][q]  = __float_as_uint(AsIm[rr*ZPITCH + cc]);
                        as_[mt][q] = __float_as_uint(AsSu[rr*ZPITCH + cc]);
                    }
                }
            }
            uint32_t br[4][2], bi[4][2], bs[4][2];
#pragma unroll
            for (int nt = 0; nt < 4; nt++){
                int n = nwarp*32 + nt*8 + gid;
#pragma unroll
                for (int q = 0; q < 2; q++){
                    int cc = kk + tig + q*4;
                    br[nt][q] = __float_as_uint(BsRe[n*ZPITCH + cc]);
                    if (!realk){
                        bi[nt][q] = __float_as_uint(BsIm[n*ZPITCH + cc]);
                        bs[nt][q] = __float_as_uint(BsSu[n*ZPITCH + cc]);
                    }
                }
            }
            if (realk){
#pragma unroll
                for (int mt = 0; mt < 2; mt++)
#pragma unroll
                    for (int nt = 0; nt < 4; nt++)
                        mma_tf32(p1[mt][nt], ar[mt], br[nt]);
            } else {
#pragma unroll
                for (int mt = 0; mt < 2; mt++)
#pragma unroll
                    for (int nt = 0; nt < 4; nt++){
                        mma_tf32(p1[mt][nt], ar[mt],  br[nt]);
                        mma_tf32(p2[mt][nt], ai[mt],  bi[nt]);
                        mma_tf32(p3[mt][nt], as_[mt], bs[nt]);
                    }
            }
        }
        __syncthreads();
        if (c + 2 < 8) issue(c + 2, st);
        CPCOMMIT();
    }

    // ---- epilogue ----
    float* Csr = (float*)smemc;              // [128][68]
    float* Csi = Csr + 128*68;
#pragma unroll
    for (int mt = 0; mt < 2; mt++){
        int r0 = mwarp*32 + mt*16 + gid;
#pragma unroll
        for (int nt = 0; nt < 4; nt++){
            int col = nwarp*32 + nt*8 + tig*2;
#pragma unroll
            for (int hh = 0; hh < 2; hh++){
                int row = r0 + hh*8;
                float2 vr, vi;
                if (realk){
                    vr.x = p1[mt][nt][hh*2+0]; vr.y = p1[mt][nt][hh*2+1];
                    vi.x = 0.f; vi.y = 0.f;
                } else {
                    float a1 = p1[mt][nt][hh*2+0], a2 = p1[mt][nt][hh*2+1];
                    float b1 = p2[mt][nt][hh*2+0], b2 = p2[mt][nt][hh*2+1];
                    float c1 = p3[mt][nt][hh*2+0], c2 = p3[mt][nt][hh*2+1];
                    vr.x = a1 - b1;       vr.y = a2 - b2;
                    vi.x = c1 - a1 - b1;  vi.y = c2 - a2 - b2;
                }
                *(float2*)&Csr[row*68 + col] = vr;
                *(float2*)&Csi[row*68 + col] = vi;
            }
        }
    }
    __syncthreads();
#pragma unroll
    for (int h = 0; h < 8; h++){
        int lin = h*256 + tid;
        int row = lin >> 4, c4 = (lin & 15)*4;
        float4 vr = *(const float4*)&Csr[row*68 + c4];
        float4 vi = *(const float4*)&Csi[row*68 + c4];
        *(float4*)(Cr + (size_t)(i0 + row)*NMAT + n0 + c4) = vr;
        *(float4*)(Ci + (size_t)(i0 + row)*NMAT + n0 + c4) = vi;
    }
}

// ---------------- Stage 3: inverse rDFT (pair-split, smem-staged stores) ----------------
__global__ void __launch_bounds__(256) idft_kernel(float* __restrict__ out){
    __shared__ float sm[128*67];
    const int tid  = threadIdx.x;
    const int tube = tid & 127;
    const int T = blockIdx.x*128 + tube;
    const int b = T >> 16;
    const int idx = T & 65535;
    const float* __restrict__ cr = g_Cr + ((size_t)b*NFREQ << 16) + idx;
    const float* __restrict__ ci = g_Ci + ((size_t)b*NFREQ << 16) + idx;
    float* sw = &sm[tube*67];

    if (tid < 128){
        // even outputs: RP, IM, R0, R16, R32
        float R0  = cr[0];
        float R16 = cr[(size_t)16 << 16];
        float R32 = cr[(size_t)32 << 16];
        float RP[16], IM[16];
#pragma unroll
        for (int k = 1; k < 16; k++){
            RP[k] = cr[(size_t)k << 16] + cr[(size_t)(32-k) << 16];
            IM[k] = ci[(size_t)k << 16] - ci[(size_t)(32-k) << 16];
        }
        InvE<16>::run(R0, R16, R32, RP, IM, sw);
    } else {
        // odd outputs: RM, IP, R0-R32, I16
        float RD  = cr[0] - cr[(size_t)32 << 16];
        float I16 = ci[(size_t)16 << 16];
        float RM[16], IP[16];
#pragma unroll
        for (int k = 1; k < 16; k++){
            RM[k] = cr[(size_t)k << 16] - cr[(size_t)(32-k) << 16];
            IP[k] = ci[(size_t)k << 16] + ci[(size_t)(32-k) << 16];
        }
        InvO<15>::run(RD, I16, RM, IP, sw);
    }
    __syncthreads();
    float4* out4 = (float4*)(out + (size_t)blockIdx.x * 8192);
#pragma unroll
    for (int h = 0; h < 8; h++){
        int l4 = h*256 + tid;
        int tb = l4 >> 4;
        int s4 = l4 & 15;
        const float* p = &sm[tb*67 + s4*4];
        float4 v; v.x = p[0]; v.y = p[1]; v.z = p[2]; v.w = p[3];
        out4[l4] = v;
    }
}

// ---------------- launch ----------------
extern "C" void kernel_launch(void* const* d_in, const int* in_sizes, int n_in,
                              void* d_out, int out_size){
    const float* A = (const float*)d_in[0];
    const float* B = (const float*)d_in[1];
    float* out = (float*)d_out;

    cudaFuncSetAttribute(zgemm_mma, cudaFuncAttributeMaxDynamicSharedMemorySize, ZSMEM);

    dft_fwd_A<<<NTUBE/128, 128>>>(A);
    dft_fwd_B<<<NTUBE/128, 128>>>(B);
    zgemm_mma<<<dim3(8, 8*NFREQ), 256, ZSMEM>>>();
    idft_kernel<<<NTUBE/128, 256>>>(out);
}